// round 13
// baseline (speedup 1.0000x reference)
#include <cuda_runtime.h>
#include <cuda_bf16.h>
#include <cstdint>

#define BATCH   1024
#define NCOL    64
#define NCOND   64
#define NRODT   1024
#define NEST    128
#define NFOREST 100
#define NHID    128
#define NCLASS  10
#define EPSF    1e-5f
#define CB      16          // batch rows per cond block

// smem layout: B1 buffer + small B3 tile, 144-word rows
// (stride ≡ 16 mod 32 -> conflict-free LDS.128)
#define SWC   144
#define W_B1  0
#define W_B3  18432         // 128*144
#define SMEM_WORDS 20736    // 82,944 bytes -> 2 blocks/SM

// ---------------- scratch ---------------------------------------------------
__device__ float g_W  [BATCH * NRODT];
__device__ float g_rmax[BATCH];
__device__ float g_EWT[NRODT * BATCH];            // exp(w-rowmax), [g][b]
__device__ float g_Y  [(size_t)NFOREST * BATCH * NCLASS];
__device__ uint32_t g_EsC[NFOREST * 16384];       // B1 combined [n][128w] per forest
__device__ uint32_t g_L1C[16384];                 // B2 combined (read via L1D)
__device__ uint32_t g_L2C[2048];                  // B3 combined (16 rows x 128w)

// ---------------- helpers ----------------------------------------------------
__device__ __forceinline__ uint32_t pack_bf16(float a, float b) {
    __nv_bfloat16 ha = __float2bfloat16(a), hb = __float2bfloat16(b);
    return (uint32_t)__bfloat16_as_ushort(ha)
         | ((uint32_t)__bfloat16_as_ushort(hb) << 16);
}
__device__ __forceinline__ void split2(float a, float b,
                                       uint32_t& hi, uint32_t& lo) {
    __nv_bfloat16 ha = __float2bfloat16(a), hb = __float2bfloat16(b);
    float ra = a - __bfloat162float(ha);
    float rb = b - __bfloat162float(hb);
    hi = (uint32_t)__bfloat16_as_ushort(ha)
       | ((uint32_t)__bfloat16_as_ushort(hb) << 16);
    lo = pack_bf16(ra, rb);
}
__device__ __forceinline__ void mma_bf16(float* c,
    uint32_t a0, uint32_t a1, uint32_t a2, uint32_t a3,
    uint32_t b0, uint32_t b1) {
    asm volatile(
        "mma.sync.aligned.m16n8k16.row.col.f32.bf16.bf16.f32 "
        "{%0,%1,%2,%3},{%4,%5,%6,%7},{%8,%9},{%0,%1,%2,%3};"
        : "+f"(c[0]), "+f"(c[1]), "+f"(c[2]), "+f"(c[3])
        : "r"(a0), "r"(a1), "r"(a2), "r"(a3), "r"(b0), "r"(b1));
}
__device__ __forceinline__ float fast_sigmoid(float x) {
    float th;
    asm("tanh.approx.f32 %0, %1;" : "=f"(th) : "f"(x * 0.5f));
    return fmaf(0.5f, th, 0.5f);
}
__device__ __forceinline__ uint32_t smem_u32(const void* p) {
    uint32_t a;
    asm("{ .reg .u64 t; cvta.to.shared.u64 t, %1; cvt.u32.u64 %0, t; }"
        : "=r"(a) : "l"(p));
    return a;
}
__device__ __forceinline__ void cp16(uint32_t dst, const void* src) {
    asm volatile("cp.async.cg.shared.global [%0], [%1], 16;"
                 :: "r"(dst), "l"(src));
}
#define CP_COMMIT() asm volatile("cp.async.commit_group;" ::: "memory")
#define CP_WAIT(n)  asm volatile("cp.async.wait_group %0;" :: "n"(n) : "memory")

// ---------------------------------------------------------------------------
// Kernel 1: condition generation, 16 batch rows per block (param reuse)
// ---------------------------------------------------------------------------
__global__ void __launch_bounds__(256) cond_kernel(
    const float* __restrict__ x,    const float* __restrict__ w1,
    const float* __restrict__ b1,   const int*   __restrict__ perm,
    const float* __restrict__ gn1g, const float* __restrict__ gn1b,
    const float* __restrict__ w2a,  const float* __restrict__ b2a,
    const float* __restrict__ gn2g, const float* __restrict__ gn2b,
    const float* __restrict__ w2b,  const float* __restrict__ b2b)
{
    __shared__ float xs[CB][NCOL];
    const int t  = threadIdx.x;
    const int g  = blockIdx.x * 256 + t;
    const int b0 = blockIdx.y * CB;

    ((float4*)&xs[0][0])[t] = ((const float4*)(x + b0 * NCOL))[t];

    const int4 p4 = ((const int4*)perm)[g];
    const int pv[4] = {p4.x, p4.y, p4.z, p4.w};
    float w1v[4], b1v[4];
    int   col[4];
#pragma unroll
    for (int i = 0; i < 4; i++) {
        col[i] = pv[i] & 63;
        const int wi = col[i] * NCOND + (pv[i] >> 6);
        w1v[i] = w1[wi]; b1v[i] = b1[wi];
    }
    const float4 g1  = ((const float4*)gn1g)[g];
    const float4 be1 = ((const float4*)gn1b)[g];
    const float4 bb2 = ((const float4*)b2a)[g];
    const float4 wr0 = ((const float4*)w2a)[g * 4 + 0];
    const float4 wr1 = ((const float4*)w2a)[g * 4 + 1];
    const float4 wr2 = ((const float4*)w2a)[g * 4 + 2];
    const float4 wr3 = ((const float4*)w2a)[g * 4 + 3];
    const float4 g2  = ((const float4*)gn2g)[g];
    const float4 be2 = ((const float4*)gn2b)[g];
    const float4 wb  = ((const float4*)w2b)[g];
    const float bb   = b2b[g];
    __syncthreads();

#pragma unroll 2
    for (int r = 0; r < CB; r++) {
        float o[4];
#pragma unroll
        for (int i = 0; i < 4; i++)
            o[i] = fast_sigmoid(fmaf(xs[r][col[i]], w1v[i], b1v[i]));

        float mu = 0.f, s2 = 0.f;
#pragma unroll
        for (int i = 0; i < 4; i++) { mu += o[i]; s2 += o[i] * o[i]; }
        mu *= 0.25f; s2 = s2 * 0.25f - mu * mu;
        const float rstd = rsqrtf(s2 + EPSF);
        float hn[4];
        hn[0] = (o[0] - mu) * rstd * g1.x + be1.x;
        hn[1] = (o[1] - mu) * rstd * g1.y + be1.y;
        hn[2] = (o[2] - mu) * rstd * g1.z + be1.z;
        hn[3] = (o[3] - mu) * rstd * g1.w + be1.w;

        float h2[4] = {bb2.x, bb2.y, bb2.z, bb2.w};
        h2[0] = fmaf(hn[0], wr0.x, h2[0]); h2[1] = fmaf(hn[0], wr0.y, h2[1]);
        h2[2] = fmaf(hn[0], wr0.z, h2[2]); h2[3] = fmaf(hn[0], wr0.w, h2[3]);
        h2[0] = fmaf(hn[1], wr1.x, h2[0]); h2[1] = fmaf(hn[1], wr1.y, h2[1]);
        h2[2] = fmaf(hn[1], wr1.z, h2[2]); h2[3] = fmaf(hn[1], wr1.w, h2[3]);
        h2[0] = fmaf(hn[2], wr2.x, h2[0]); h2[1] = fmaf(hn[2], wr2.y, h2[1]);
        h2[2] = fmaf(hn[2], wr2.z, h2[2]); h2[3] = fmaf(hn[2], wr2.w, h2[3]);
        h2[0] = fmaf(hn[3], wr3.x, h2[0]); h2[1] = fmaf(hn[3], wr3.y, h2[1]);
        h2[2] = fmaf(hn[3], wr3.z, h2[2]); h2[3] = fmaf(hn[3], wr3.w, h2[3]);
#pragma unroll
        for (int i = 0; i < 4; i++) h2[i] = fmaxf(h2[i], 0.f);

        float mu2 = 0.f, t2 = 0.f;
#pragma unroll
        for (int i = 0; i < 4; i++) { mu2 += h2[i]; t2 += h2[i] * h2[i]; }
        mu2 *= 0.25f; t2 = t2 * 0.25f - mu2 * mu2;
        const float rstd2 = rsqrtf(t2 + EPSF);
        float wv = bb;
        wv = fmaf((h2[0] - mu2) * rstd2 * g2.x + be2.x, wb.x, wv);
        wv = fmaf((h2[1] - mu2) * rstd2 * g2.y + be2.y, wb.y, wv);
        wv = fmaf((h2[2] - mu2) * rstd2 * g2.z + be2.z, wb.z, wv);
        wv = fmaf((h2[3] - mu2) * rstd2 * g2.w + be2.w, wb.w, wv);
        g_W[(b0 + r) * NRODT + g] = wv;
    }
}

// ---------------------------------------------------------------------------
// rowmax: warp per batch row
// ---------------------------------------------------------------------------
__global__ void rowmax_kernel()
{
    const int b = blockIdx.x * 8 + (threadIdx.x >> 5);
    const int lane = threadIdx.x & 31;
    const float4* p = (const float4*)(g_W + b * NRODT);
    float m = -1e30f;
#pragma unroll
    for (int j = 0; j < 8; j++) {
        const float4 v = p[lane + j * 32];
        m = fmaxf(m, fmaxf(fmaxf(v.x, v.y), fmaxf(v.z, v.w)));
    }
#pragma unroll
    for (int o = 16; o > 0; o >>= 1)
        m = fmaxf(m, __shfl_xor_sync(0xffffffffu, m, o));
    if (lane == 0) g_rmax[b] = m;
}

// fused exp + transpose: g_EWT[g][b] = exp(g_W[b][g] - rmax[b])
__global__ void expT_kernel()
{
    __shared__ float tile[32][33];
    const int bx = blockIdx.x * 32, by = blockIdx.y * 32;
    const int tx = threadIdx.x, ty = threadIdx.y;   // 32 x 8
#pragma unroll
    for (int j = 0; j < 32; j += 8) {
        const int b = by + ty + j;
        tile[ty + j][tx] = __expf(g_W[b * NRODT + bx + tx] - g_rmax[b]);
    }
    __syncthreads();
#pragma unroll
    for (int j = 0; j < 32; j += 8)
        g_EWT[(bx + ty + j) * BATCH + by + tx] = tile[tx][ty + j];
}

// ---------------------------------------------------------------------------
// Prep: build combined B tiles. Per (row n, cell(ks,tg)): one uint4 store
// {hi(kw), hi(kw+4), lo(kw), lo(kw+4)},  kw = ks*8+tg.
// ---------------------------------------------------------------------------
__global__ void prep_es(const float* __restrict__ E, const int* __restrict__ swr)
{
    __shared__ int idx[NEST];
    const int f = blockIdx.x;
    const int t = threadIdx.x;            // row n = hidden channel
    if (t < NEST) idx[t] = swr[f * NEST + t];
    __syncthreads();
    uint32_t* rowP = g_EsC + f * 16384 + t * 128;
#pragma unroll
    for (int c = 0; c < 2; c++) {
        const int cell = blockIdx.y * 2 + c;       // 0..31
        const int ks = cell >> 2, tg = cell & 3;
        const int kw = ks * 8 + tg;
        const float v0 = __ldg(&E[(size_t)idx[2 * kw]     * NHID + t]);
        const float v1 = __ldg(&E[(size_t)idx[2 * kw + 1] * NHID + t]);
        const float v2 = __ldg(&E[(size_t)idx[2 * kw + 8] * NHID + t]);
        const float v3 = __ldg(&E[(size_t)idx[2 * kw + 9] * NHID + t]);
        uint32_t ha, la, hb, lb;
        split2(v0, v1, ha, la);
        split2(v2, v3, hb, lb);
        *(uint4*)(rowP + ks * 16 + tg * 4) = make_uint4(ha, hb, la, lb);
    }
}
__global__ void prep_l1(const float* __restrict__ lin1w)
{
    const int t = threadIdx.x;            // row n = h2
    uint32_t* rowP = g_L1C + t * 128;
#pragma unroll
    for (int c = 0; c < 4; c++) {
        const int cell = blockIdx.x * 4 + c;
        const int ks = cell >> 2, tg = cell & 3;
        const int kw = ks * 8 + tg;
        const float v0 = lin1w[(2 * kw) * NHID + t];
        const float v1 = lin1w[(2 * kw + 1) * NHID + t];
        const float v2 = lin1w[(2 * kw + 8) * NHID + t];
        const float v3 = lin1w[(2 * kw + 9) * NHID + t];
        uint32_t ha, la, hb, lb;
        split2(v0, v1, ha, la);
        split2(v2, v3, hb, lb);
        *(uint4*)(rowP + ks * 16 + tg * 4) = make_uint4(ha, hb, la, lb);
    }
}
__global__ void prep_l2(const float* __restrict__ lin2w)
{
    const int n = blockIdx.x;             // 0..15 (padded class)
    const int cell = threadIdx.x;         // 0..31
    const int ks = cell >> 2, tg = cell & 3;
    const int kw = ks * 8 + tg;
    const bool ok = (n < NCLASS);
    const float v0 = ok ? lin2w[(2 * kw) * NCLASS + n] : 0.f;
    const float v1 = ok ? lin2w[(2 * kw + 1) * NCLASS + n] : 0.f;
    const float v2 = ok ? lin2w[(2 * kw + 8) * NCLASS + n] : 0.f;
    const float v3 = ok ? lin2w[(2 * kw + 9) * NCLASS + n] : 0.f;
    uint32_t ha, la, hb, lb;
    split2(v0, v1, ha, la);
    split2(v2, v3, hb, lb);
    *(uint4*)(g_L2C + n * 128 + ks * 16 + tg * 4) = make_uint4(ha, hb, la, lb);
}

// ---------------------------------------------------------------------------
// Kernel 2: HMMA forest kernel.  Block = (128-row tile, forest f), 8 warps,
// 2 blocks/SM.  B1 (Es) in smem; B2 (lin1w) read straight from global
// through L1D (identical for all blocks, 64 KB tile fits the carveout);
// B3 in smem.  A fragments fully register-resident.  No mid-kernel barriers.
// ---------------------------------------------------------------------------
__global__ void __launch_bounds__(256, 2) forest_mma(
    const int*   __restrict__ swr,
    const float* __restrict__ ln1g, const float* __restrict__ ln1b,
    const float* __restrict__ lin1b,
    const float* __restrict__ ln2g, const float* __restrict__ ln2b,
    const float* __restrict__ lin2b)
{
    extern __shared__ __align__(16) uint32_t sw4[];
    __shared__ float pg1[128], pb1[128], plb[128], pg2[128], pb2[128];
    __shared__ float pl2b[16];
    __shared__ int idxs[NEST];

    const int t = threadIdx.x;
    const int f = blockIdx.y;
    const int b0 = blockIdx.x * 128;
    const int w = t >> 5, lane = t & 31, g = lane >> 2, tg = lane & 3;
    const int mbase = w * 16;
    const uint32_t dbase = smem_u32(sw4);

    // ---- async copies: B1 (Es) + B3 into smem (cp.async.cg: L1-bypassing) ----
    {
        const uint4* s1 = (const uint4*)(g_EsC + f * 16384);
        for (int i = t; i < 4096; i += 256) {
            const int n = i >> 5, q = i & 31;
            cp16(dbase + (uint32_t)(W_B1 + n * SWC) * 4 + (uint32_t)q * 16,
                 s1 + i);
        }
        const uint4* s3 = (const uint4*)g_L2C;
        for (int i = t; i < 512; i += 256) {
            const int n = i >> 5, q = i & 31;
            cp16(dbase + (uint32_t)(W_B3 + n * SWC) * 4 + (uint32_t)q * 16,
                 s3 + i);
        }
        CP_COMMIT();
    }

    if (t < 128) {
        idxs[t] = swr[f * NEST + t];
        pg1[t] = ln1g[t]; pb1[t] = ln1b[t];
        plb[t] = lin1b[t];
        pg2[t] = ln2g[t]; pb2[t] = ln2b[t];
    }
    if (t < 16) pl2b[t] = (t < NCLASS) ? lin2b[t] : 0.f;
    __syncthreads();   // idxs visible for gather

    // ---- gather A1 fragments DIRECTLY into registers + row sums ----
    uint32_t Ah[16], Al[16], Bh[16], Bl[16];   // rows rA / rA+8, word slots
    float SA, SB;
    {
        const int rA = b0 + mbase + g;     // global batch row (and rA+8)
        float sA = 0.f, sB = 0.f;
#pragma unroll
        for (int ks = 0; ks < 8; ks++) {
            const int kw = ks * 8 + tg;
            const float* p0 = g_EWT + (size_t)idxs[2 * kw]     * BATCH + rA;
            const float* p1 = g_EWT + (size_t)idxs[2 * kw + 1] * BATCH + rA;
            const float* p2 = g_EWT + (size_t)idxs[2 * kw + 8] * BATCH + rA;
            const float* p3 = g_EWT + (size_t)idxs[2 * kw + 9] * BATCH + rA;
            const float a0 = p0[0], a0b = p0[8];
            const float a1 = p1[0], a1b = p1[8];
            const float a2 = p2[0], a2b = p2[8];
            const float a3 = p3[0], a3b = p3[8];
            sA += a0 + a1 + a2 + a3;
            sB += a0b + a1b + a2b + a3b;
            split2(a0, a1, Ah[2 * ks],     Al[2 * ks]);
            split2(a2, a3, Ah[2 * ks + 1], Al[2 * ks + 1]);
            split2(a0b, a1b, Bh[2 * ks],     Bl[2 * ks]);
            split2(a2b, a3b, Bh[2 * ks + 1], Bl[2 * ks + 1]);
        }
        sA += __shfl_xor_sync(0xffffffffu, sA, 1);
        sA += __shfl_xor_sync(0xffffffffu, sA, 2);
        sB += __shfl_xor_sync(0xffffffffu, sB, 1);
        sB += __shfl_xor_sync(0xffffffffu, sB, 2);
        SA = sA; SB = sB;
    }
    CP_WAIT(0);        // B1 + B3 landed
    __syncthreads();

    // =============== GEMM1: D = A1 @ B1 (Es, smem) ===============
    float C[16][4];
#pragma unroll
    for (int nt = 0; nt < 16; nt++)
#pragma unroll
        for (int j = 0; j < 4; j++) C[nt][j] = 0.f;

#pragma unroll
    for (int ks = 0; ks < 8; ks++) {
        const uint32_t ah0 = Ah[2 * ks],     ah1 = Bh[2 * ks];
        const uint32_t ah2 = Ah[2 * ks + 1], ah3 = Bh[2 * ks + 1];
        const uint32_t al0 = Al[2 * ks],     al1 = Bl[2 * ks];
        const uint32_t al2 = Al[2 * ks + 1], al3 = Bl[2 * ks + 1];
#pragma unroll
        for (int nt = 0; nt < 16; nt++) {
            const uint4 q = *(const uint4*)(sw4 + W_B1 + (nt * 8 + g) * SWC
                                            + ks * 16 + tg * 4);
            mma_bf16(C[nt], ah0, ah1, ah2, ah3, q.x, q.y);
            mma_bf16(C[nt], ah0, ah1, ah2, ah3, q.z, q.w);
            mma_bf16(C[nt], al0, al1, al2, al3, q.x, q.y);
        }
    }

    // ---- epilogue 1: /S, LN1 -> refill A fragment registers ----
    {
        const float iA = 1.f / SA, iB = 1.f / SB;
        float sA = 0.f, qA = 0.f, sB = 0.f, qB = 0.f;
#pragma unroll
        for (int nt = 0; nt < 16; nt++) {
            C[nt][0] *= iA; C[nt][1] *= iA;
            C[nt][2] *= iB; C[nt][3] *= iB;
            sA += C[nt][0] + C[nt][1];
            qA += C[nt][0] * C[nt][0] + C[nt][1] * C[nt][1];
            sB += C[nt][2] + C[nt][3];
            qB += C[nt][2] * C[nt][2] + C[nt][3] * C[nt][3];
        }
#pragma unroll
        for (int o = 1; o <= 2; o <<= 1) {
            sA += __shfl_xor_sync(0xffffffffu, sA, o);
            qA += __shfl_xor_sync(0xffffffffu, qA, o);
            sB += __shfl_xor_sync(0xffffffffu, sB, o);
            qB += __shfl_xor_sync(0xffffffffu, qB, o);
        }
        const float mA = sA * (1.f / NHID);
        const float rA = rsqrtf(qA * (1.f / NHID) - mA * mA + EPSF);
        const float mB = sB * (1.f / NHID);
        const float rB = rsqrtf(qB * (1.f / NHID) - mB * mB + EPSF);
#pragma unroll
        for (int nt = 0; nt < 16; nt++) {
            const int n0 = nt * 8 + tg * 2, n1 = n0 + 1;
            const float zA0 = (C[nt][0] - mA) * rA * pg1[n0] + pb1[n0];
            const float zA1 = (C[nt][1] - mA) * rA * pg1[n1] + pb1[n1];
            const float zB0 = (C[nt][2] - mB) * rB * pg1[n0] + pb1[n0];
            const float zB1 = (C[nt][3] - mB) * rB * pg1[n1] + pb1[n1];
            split2(zA0, zA1, Ah[nt], Al[nt]);
            split2(zB0, zB1, Bh[nt], Bl[nt]);
        }
    }
    // no barrier: GEMM2 uses registers (A) + global L1D (B2)

    // =============== GEMM2: D = z1 @ lin1w (B from global via L1D) ==========
#pragma unroll
    for (int nt = 0; nt < 16; nt++)
#pragma unroll
        for (int j = 0; j < 4; j++) C[nt][j] = 0.f;

#pragma unroll
    for (int ks = 0; ks < 8; ks++) {
        const uint32_t ah0 = Ah[2 * ks],     ah1 = Bh[2 * ks];
        const uint32_t ah2 = Ah[2 * ks + 1], ah3 = Bh[2 * ks + 1];
        const uint32_t al0 = Al[2 * ks],     al1 = Bl[2 * ks];
        const uint32_t al2 = Al[2 * ks + 1], al3 = Bl[2 * ks + 1];
#pragma unroll
        for (int nt = 0; nt < 16; nt++) {
            const uint4 q = __ldg((const uint4*)(g_L1C + (nt * 8 + g) * 128
                                                 + ks * 16 + tg * 4));
            mma_bf16(C[nt], ah0, ah1, ah2, ah3, q.x, q.y);
            mma_bf16(C[nt], ah0, ah1, ah2, ah3, q.z, q.w);
            mma_bf16(C[nt], al0, al1, al2, al3, q.x, q.y);
        }
    }

    // ---- epilogue 2: +bias, ReLU, LN2 -> A fragment registers ----
    {
        float sA = 0.f, qA = 0.f, sB = 0.f, qB = 0.f;
#pragma unroll
        for (int nt = 0; nt < 16; nt++) {
            const int n0 = nt * 8 + tg * 2, n1 = n0 + 1;
            C[nt][0] = fmaxf(C[nt][0] + plb[n0], 0.f);
            C[nt][1] = fmaxf(C[nt][1] + plb[n1], 0.f);
            C[nt][2] = fmaxf(C[nt][2] + plb[n0], 0.f);
            C[nt][3] = fmaxf(C[nt][3] + plb[n1], 0.f);
            sA += C[nt][0] + C[nt][1];
            qA += C[nt][0] * C[nt][0] + C[nt][1] * C[nt][1];
            sB += C[nt][2] + C[nt][3];
            qB += C[nt][2] * C[nt][2] + C[nt][3] * C[nt][3];
        }
#pragma unroll
        for (int o = 1; o <= 2; o <<= 1) {
            sA += __shfl_xor_sync(0xffffffffu, sA, o);
            qA += __shfl_xor_sync(0xffffffffu, qA, o);
            sB += __shfl_xor_sync(0xffffffffu, sB, o);
            qB += __shfl_xor_sync(0xffffffffu, qB, o);
        }
        const float mA = sA * (1.f / NHID);
        const float rA = rsqrtf(qA * (1.f / NHID) - mA * mA + EPSF);
        const float mB = sB * (1.f / NHID);
        const float rB = rsqrtf(qB * (1.f / NHID) - mB * mB + EPSF);
#pragma unroll
        for (int nt = 0; nt < 16; nt++) {
            const int n0 = nt * 8 + tg * 2, n1 = n0 + 1;
            const float zA0 = (C[nt][0] - mA) * rA * pg2[n0] + pb2[n0];
            const float zA1 = (C[nt][1] - mA) * rA * pg2[n1] + pb2[n1];
            const float zB0 = (C[nt][2] - mB) * rB * pg2[n0] + pb2[n0];
            const float zB1 = (C[nt][3] - mB) * rB * pg2[n1] + pb2[n1];
            split2(zA0, zA1, Ah[nt], Al[nt]);
            split2(zB0, zB1, Bh[nt], Bl[nt]);
        }
    }

    // =============== GEMM3: logits = z2 @ lin2w (N=16 padded, smem) =========
    float Y[2][4];
#pragma unroll
    for (int nt = 0; nt < 2; nt++)
#pragma unroll
        for (int j = 0; j < 4; j++) Y[nt][j] = 0.f;

#pragma unroll
    for (int ks = 0; ks < 8; ks++) {
        const uint32_t ah0 = Ah[2 * ks],     ah1 = Bh[2 * ks];
        const uint32_t ah2 = Ah[2 * ks + 1], ah3 = Bh[2 * ks + 1];
        const uint32_t al0 = Al[2 * ks],     al1 = Bl[2 * ks];
        const uint32_t al2 = Al[2 * ks + 1], al3 = Bl[2 * ks + 1];
#pragma unroll
        for (int nt = 0; nt < 2; nt++) {
            const uint4 q = *(const uint4*)(sw4 + W_B3 + (nt * 8 + g) * SWC
                                            + ks * 16 + tg * 4);
            mma_bf16(Y[nt], ah0, ah1, ah2, ah3, q.x, q.y);
            mma_bf16(Y[nt], ah0, ah1, ah2, ah3, q.z, q.w);
            mma_bf16(Y[nt], al0, al1, al2, al3, q.x, q.y);
        }
    }

    // ---- write logits ----
    {
        float* yA = g_Y + ((size_t)f * BATCH + b0 + mbase + g) * NCLASS;
        float* yB = g_Y + ((size_t)f * BATCH + b0 + mbase + g + 8) * NCLASS;
#pragma unroll
        for (int nt = 0; nt < 2; nt++) {
            const int n0 = nt * 8 + tg * 2, n1 = n0 + 1;
            if (n0 < NCLASS) {
                yA[n0] = Y[nt][0] + pl2b[n0];
                yB[n0] = Y[nt][2] + pl2b[n0];
            }
            if (n1 < NCLASS) {
                yA[n1] = Y[nt][1] + pl2b[n1];
                yB[n1] = Y[nt][3] + pl2b[n1];
            }
        }
    }
}

// ---------------------------------------------------------------------------
// Kernel 3: mean over forests, 4-way f-split per block
// ---------------------------------------------------------------------------
__global__ void mean_kernel(float* __restrict__ out)
{
    __shared__ float part[4][64];
    const int t = threadIdx.x;
    const int i = blockIdx.x * 64 + (t & 63);
    const int fg = t >> 6;
    float s = 0.f;
#pragma unroll 5
    for (int f = fg * 25; f < fg * 25 + 25; f++)
        s += g_Y[(size_t)f * (BATCH * NCLASS) + i];
    part[fg][t & 63] = s;
    __syncthreads();
    if (t < 64)
        out[blockIdx.x * 64 + t] =
            (part[0][t] + part[1][t] + part[2][t] + part[3][t]) * (1.f / NFOREST);
}

// ---------------------------------------------------------------------------
extern "C" void kernel_launch(void* const* d_in, const int* in_sizes, int n_in,
                              void* d_out, int out_size)
{
    const float* x     = (const float*)d_in[0];
    const float* w1    = (const float*)d_in[1];
    const float* b1    = (const float*)d_in[2];
    const int*   perm  = (const int*)  d_in[3];
    const float* gn1g  = (const float*)d_in[4];
    const float* gn1b  = (const float*)d_in[5];
    const float* w2a   = (const float*)d_in[6];
    const float* b2a   = (const float*)d_in[7];
    const float* gn2g  = (const float*)d_in[8];
    const float* gn2b  = (const float*)d_in[9];
    const float* w2b   = (const float*)d_in[10];
    const float* b2b   = (const float*)d_in[11];
    const float* E     = (const float*)d_in[12];
    const int*   swr   = (const int*)  d_in[13];
    const float* ln1g  = (const float*)d_in[14];
    const float* ln1b  = (const float*)d_in[15];
    const float* lin1w = (const float*)d_in[16];
    const float* lin1b = (const float*)d_in[17];
    const float* ln2g  = (const float*)d_in[18];
    const float* ln2b  = (const float*)d_in[19];
    const float* lin2w = (const float*)d_in[20];
    const float* lin2b = (const float*)d_in[21];

    const int dyn_smem = SMEM_WORDS * 4;   // 82,944 B -> 2 blocks/SM
    cudaFuncSetAttribute(forest_mma,
                         cudaFuncAttributeMaxDynamicSharedMemorySize, dyn_smem);

    cond_kernel<<<dim3(NRODT / 256, BATCH / CB), 256>>>(
        x, w1, b1, perm, gn1g, gn1b, w2a, b2a, gn2g, gn2b, w2b, b2b);
    rowmax_kernel<<<BATCH / 8, 256>>>();
    expT_kernel<<<dim3(NRODT / 32, BATCH / 32), dim3(32, 8)>>>();
    prep_es<<<dim3(NFOREST, 16), 128>>>(E, swr);
    prep_l1<<<8, 128>>>(lin1w);
    prep_l2<<<16, 32>>>(lin2w);

    forest_mma<<<dim3(BATCH / 128, NFOREST), 256, dyn_smem>>>(
        swr, ln1g, ln1b, lin1b, ln2g, ln2b, lin2b);

    mean_kernel<<<BATCH * NCLASS / 64, 256>>>((float*)d_out);
}

// round 15
// speedup vs baseline: 1.0432x; 1.0432x over previous
#include <cuda_runtime.h>
#include <cuda_bf16.h>
#include <cstdint>

#define BATCH   1024
#define NCOL    64
#define NCOND   64
#define NRODT   1024
#define NEST    128
#define NFOREST 100
#define NHID    128
#define NCLASS  10
#define EPSF    1e-5f
#define CB      16          // batch rows per cond block

// smem layout: ONE shared B buffer (B1 then B2), 144-word rows
// (stride ≡ 16 mod 32 -> conflict-free LDS.128), plus small B3 tile.
#define SWC   144
#define W_BUF 0
#define W_B3  18432         // 128*144
#define SMEM_WORDS 20736    // 82,944 bytes -> 2 blocks/SM

// ---------------- scratch ---------------------------------------------------
__device__ float g_W  [BATCH * NRODT];
__device__ float g_rmax[BATCH];
__device__ float g_EWT[NRODT * BATCH];            // exp(w-rowmax), [g][b]
__device__ float g_Y  [(size_t)NFOREST * BATCH * NCLASS];
__device__ uint32_t g_EsC[NFOREST * 16384];       // B1 combined [n][128w] per forest
__device__ uint32_t g_L1C[16384];                 // B2 combined
__device__ uint32_t g_L2C[2048];                  // B3 combined (16 rows x 128w)

// ---------------- helpers ----------------------------------------------------
__device__ __forceinline__ uint32_t pack_bf16(float a, float b) {
    __nv_bfloat16 ha = __float2bfloat16(a), hb = __float2bfloat16(b);
    return (uint32_t)__bfloat16_as_ushort(ha)
         | ((uint32_t)__bfloat16_as_ushort(hb) << 16);
}
__device__ __forceinline__ void split2(float a, float b,
                                       uint32_t& hi, uint32_t& lo) {
    __nv_bfloat16 ha = __float2bfloat16(a), hb = __float2bfloat16(b);
    float ra = a - __bfloat162float(ha);
    float rb = b - __bfloat162float(hb);
    hi = (uint32_t)__bfloat16_as_ushort(ha)
       | ((uint32_t)__bfloat16_as_ushort(hb) << 16);
    lo = pack_bf16(ra, rb);
}
__device__ __forceinline__ void mma_bf16(float* c,
    uint32_t a0, uint32_t a1, uint32_t a2, uint32_t a3,
    uint32_t b0, uint32_t b1) {
    asm volatile(
        "mma.sync.aligned.m16n8k16.row.col.f32.bf16.bf16.f32 "
        "{%0,%1,%2,%3},{%4,%5,%6,%7},{%8,%9},{%0,%1,%2,%3};"
        : "+f"(c[0]), "+f"(c[1]), "+f"(c[2]), "+f"(c[3])
        : "r"(a0), "r"(a1), "r"(a2), "r"(a3), "r"(b0), "r"(b1));
}
__device__ __forceinline__ float fast_sigmoid(float x) {
    float th;
    asm("tanh.approx.f32 %0, %1;" : "=f"(th) : "f"(x * 0.5f));
    return fmaf(0.5f, th, 0.5f);
}
__device__ __forceinline__ uint32_t smem_u32(const void* p) {
    uint32_t a;
    asm("{ .reg .u64 t; cvta.to.shared.u64 t, %1; cvt.u32.u64 %0, t; }"
        : "=r"(a) : "l"(p));
    return a;
}
__device__ __forceinline__ void cp16(uint32_t dst, const void* src) {
    asm volatile("cp.async.cg.shared.global [%0], [%1], 16;"
                 :: "r"(dst), "l"(src));
}
#define CP_COMMIT() asm volatile("cp.async.commit_group;" ::: "memory")
#define CP_WAIT(n)  asm volatile("cp.async.wait_group %0;" :: "n"(n) : "memory")

// ---------------------------------------------------------------------------
// Kernel 1: condition generation, 16 batch rows per block (param reuse)
// ---------------------------------------------------------------------------
__global__ void __launch_bounds__(256) cond_kernel(
    const float* __restrict__ x,    const float* __restrict__ w1,
    const float* __restrict__ b1,   const int*   __restrict__ perm,
    const float* __restrict__ gn1g, const float* __restrict__ gn1b,
    const float* __restrict__ w2a,  const float* __restrict__ b2a,
    const float* __restrict__ gn2g, const float* __restrict__ gn2b,
    const float* __restrict__ w2b,  const float* __restrict__ b2b)
{
    __shared__ float xs[CB][NCOL];
    const int t  = threadIdx.x;
    const int g  = blockIdx.x * 256 + t;
    const int b0 = blockIdx.y * CB;

    ((float4*)&xs[0][0])[t] = ((const float4*)(x + b0 * NCOL))[t];

    const int4 p4 = ((const int4*)perm)[g];
    const int pv[4] = {p4.x, p4.y, p4.z, p4.w};
    float w1v[4], b1v[4];
    int   col[4];
#pragma unroll
    for (int i = 0; i < 4; i++) {
        col[i] = pv[i] & 63;
        const int wi = col[i] * NCOND + (pv[i] >> 6);
        w1v[i] = w1[wi]; b1v[i] = b1[wi];
    }
    const float4 g1  = ((const float4*)gn1g)[g];
    const float4 be1 = ((const float4*)gn1b)[g];
    const float4 bb2 = ((const float4*)b2a)[g];
    const float4 wr0 = ((const float4*)w2a)[g * 4 + 0];
    const float4 wr1 = ((const float4*)w2a)[g * 4 + 1];
    const float4 wr2 = ((const float4*)w2a)[g * 4 + 2];
    const float4 wr3 = ((const float4*)w2a)[g * 4 + 3];
    const float4 g2  = ((const float4*)gn2g)[g];
    const float4 be2 = ((const float4*)gn2b)[g];
    const float4 wb  = ((const float4*)w2b)[g];
    const float bb   = b2b[g];
    __syncthreads();

#pragma unroll 2
    for (int r = 0; r < CB; r++) {
        float o[4];
#pragma unroll
        for (int i = 0; i < 4; i++)
            o[i] = fast_sigmoid(fmaf(xs[r][col[i]], w1v[i], b1v[i]));

        float mu = 0.f, s2 = 0.f;
#pragma unroll
        for (int i = 0; i < 4; i++) { mu += o[i]; s2 += o[i] * o[i]; }
        mu *= 0.25f; s2 = s2 * 0.25f - mu * mu;
        const float rstd = rsqrtf(s2 + EPSF);
        float hn[4];
        hn[0] = (o[0] - mu) * rstd * g1.x + be1.x;
        hn[1] = (o[1] - mu) * rstd * g1.y + be1.y;
        hn[2] = (o[2] - mu) * rstd * g1.z + be1.z;
        hn[3] = (o[3] - mu) * rstd * g1.w + be1.w;

        float h2[4] = {bb2.x, bb2.y, bb2.z, bb2.w};
        h2[0] = fmaf(hn[0], wr0.x, h2[0]); h2[1] = fmaf(hn[0], wr0.y, h2[1]);
        h2[2] = fmaf(hn[0], wr0.z, h2[2]); h2[3] = fmaf(hn[0], wr0.w, h2[3]);
        h2[0] = fmaf(hn[1], wr1.x, h2[0]); h2[1] = fmaf(hn[1], wr1.y, h2[1]);
        h2[2] = fmaf(hn[1], wr1.z, h2[2]); h2[3] = fmaf(hn[1], wr1.w, h2[3]);
        h2[0] = fmaf(hn[2], wr2.x, h2[0]); h2[1] = fmaf(hn[2], wr2.y, h2[1]);
        h2[2] = fmaf(hn[2], wr2.z, h2[2]); h2[3] = fmaf(hn[2], wr2.w, h2[3]);
        h2[0] = fmaf(hn[3], wr3.x, h2[0]); h2[1] = fmaf(hn[3], wr3.y, h2[1]);
        h2[2] = fmaf(hn[3], wr3.z, h2[2]); h2[3] = fmaf(hn[3], wr3.w, h2[3]);
#pragma unroll
        for (int i = 0; i < 4; i++) h2[i] = fmaxf(h2[i], 0.f);

        float mu2 = 0.f, t2 = 0.f;
#pragma unroll
        for (int i = 0; i < 4; i++) { mu2 += h2[i]; t2 += h2[i] * h2[i]; }
        mu2 *= 0.25f; t2 = t2 * 0.25f - mu2 * mu2;
        const float rstd2 = rsqrtf(t2 + EPSF);
        float wv = bb;
        wv = fmaf((h2[0] - mu2) * rstd2 * g2.x + be2.x, wb.x, wv);
        wv = fmaf((h2[1] - mu2) * rstd2 * g2.y + be2.y, wb.y, wv);
        wv = fmaf((h2[2] - mu2) * rstd2 * g2.z + be2.z, wb.z, wv);
        wv = fmaf((h2[3] - mu2) * rstd2 * g2.w + be2.w, wb.w, wv);
        g_W[(b0 + r) * NRODT + g] = wv;
    }
}

// ---------------------------------------------------------------------------
// rowmax: warp per batch row
// ---------------------------------------------------------------------------
__global__ void rowmax_kernel()
{
    const int b = blockIdx.x * 8 + (threadIdx.x >> 5);
    const int lane = threadIdx.x & 31;
    const float4* p = (const float4*)(g_W + b * NRODT);
    float m = -1e30f;
#pragma unroll
    for (int j = 0; j < 8; j++) {
        const float4 v = p[lane + j * 32];
        m = fmaxf(m, fmaxf(fmaxf(v.x, v.y), fmaxf(v.z, v.w)));
    }
#pragma unroll
    for (int o = 16; o > 0; o >>= 1)
        m = fmaxf(m, __shfl_xor_sync(0xffffffffu, m, o));
    if (lane == 0) g_rmax[b] = m;
}

// fused exp + transpose: g_EWT[g][b] = exp(g_W[b][g] - rmax[b])
__global__ void expT_kernel()
{
    __shared__ float tile[32][33];
    const int bx = blockIdx.x * 32, by = blockIdx.y * 32;
    const int tx = threadIdx.x, ty = threadIdx.y;   // 32 x 8
#pragma unroll
    for (int j = 0; j < 32; j += 8) {
        const int b = by + ty + j;
        tile[ty + j][tx] = __expf(g_W[b * NRODT + bx + tx] - g_rmax[b]);
    }
    __syncthreads();
#pragma unroll
    for (int j = 0; j < 32; j += 8)
        g_EWT[(bx + ty + j) * BATCH + by + tx] = tile[tx][ty + j];
}

// ---------------------------------------------------------------------------
// Prep: build combined B tiles. Per (row n, cell(ks,tg)): one uint4 store
// {hi(kw), hi(kw+4), lo(kw), lo(kw+4)},  kw = ks*8+tg.
// ---------------------------------------------------------------------------
__global__ void prep_es(const float* __restrict__ E, const int* __restrict__ swr)
{
    __shared__ int idx[NEST];
    const int f = blockIdx.x;
    const int t = threadIdx.x;            // row n = hidden channel
    if (t < NEST) idx[t] = swr[f * NEST + t];
    __syncthreads();
    uint32_t* rowP = g_EsC + f * 16384 + t * 128;
#pragma unroll
    for (int c = 0; c < 2; c++) {
        const int cell = blockIdx.y * 2 + c;       // 0..31
        const int ks = cell >> 2, tg = cell & 3;
        const int kw = ks * 8 + tg;
        const float v0 = __ldg(&E[(size_t)idx[2 * kw]     * NHID + t]);
        const float v1 = __ldg(&E[(size_t)idx[2 * kw + 1] * NHID + t]);
        const float v2 = __ldg(&E[(size_t)idx[2 * kw + 8] * NHID + t]);
        const float v3 = __ldg(&E[(size_t)idx[2 * kw + 9] * NHID + t]);
        uint32_t ha, la, hb, lb;
        split2(v0, v1, ha, la);
        split2(v2, v3, hb, lb);
        *(uint4*)(rowP + ks * 16 + tg * 4) = make_uint4(ha, hb, la, lb);
    }
}
__global__ void prep_l1(const float* __restrict__ lin1w)
{
    const int t = threadIdx.x;            // row n = h2
    uint32_t* rowP = g_L1C + t * 128;
#pragma unroll
    for (int c = 0; c < 4; c++) {
        const int cell = blockIdx.x * 4 + c;
        const int ks = cell >> 2, tg = cell & 3;
        const int kw = ks * 8 + tg;
        const float v0 = lin1w[(2 * kw) * NHID + t];
        const float v1 = lin1w[(2 * kw + 1) * NHID + t];
        const float v2 = lin1w[(2 * kw + 8) * NHID + t];
        const float v3 = lin1w[(2 * kw + 9) * NHID + t];
        uint32_t ha, la, hb, lb;
        split2(v0, v1, ha, la);
        split2(v2, v3, hb, lb);
        *(uint4*)(rowP + ks * 16 + tg * 4) = make_uint4(ha, hb, la, lb);
    }
}
__global__ void prep_l2(const float* __restrict__ lin2w)
{
    const int n = blockIdx.x;             // 0..15 (padded class)
    const int cell = threadIdx.x;         // 0..31
    const int ks = cell >> 2, tg = cell & 3;
    const int kw = ks * 8 + tg;
    const bool ok = (n < NCLASS);
    const float v0 = ok ? lin2w[(2 * kw) * NCLASS + n] : 0.f;
    const float v1 = ok ? lin2w[(2 * kw + 1) * NCLASS + n] : 0.f;
    const float v2 = ok ? lin2w[(2 * kw + 8) * NCLASS + n] : 0.f;
    const float v3 = ok ? lin2w[(2 * kw + 9) * NCLASS + n] : 0.f;
    uint32_t ha, la, hb, lb;
    split2(v0, v1, ha, la);
    split2(v2, v3, hb, lb);
    *(uint4*)(g_L2C + n * 128 + ks * 16 + tg * 4) = make_uint4(ha, hb, la, lb);
}

// ---------------------------------------------------------------------------
// Kernel 2: HMMA forest kernel.  Block = (128-row tile, forest f), 8 warps,
// 2 blocks/SM.  B1 and B2 share one smem buffer (B2 loaded after GEMM1).
// A fragments fully register-resident.
// ---------------------------------------------------------------------------
__global__ void __launch_bounds__(256, 2) forest_mma(
    const int*   __restrict__ swr,
    const float* __restrict__ ln1g, const float* __restrict__ ln1b,
    const float* __restrict__ lin1b,
    const float* __restrict__ ln2g, const float* __restrict__ ln2b,
    const float* __restrict__ lin2b)
{
    extern __shared__ __align__(16) uint32_t sw4[];
    __shared__ float pg1[128], pb1[128], plb[128], pg2[128], pb2[128];
    __shared__ float pl2b[16];
    __shared__ int idxs[NEST];

    const int t = threadIdx.x;
    const int f = blockIdx.y;
    const int b0 = blockIdx.x * 128;
    const int w = t >> 5, lane = t & 31, g = lane >> 2, tg = lane & 3;
    const int mbase = w * 16;
    const uint32_t dbase = smem_u32(sw4);

    // ---- async copies: B1 (Es) into shared buffer, B3 small tile ----
    {
        const uint4* s1 = (const uint4*)(g_EsC + f * 16384);
        for (int i = t; i < 4096; i += 256) {
            const int n = i >> 5, q = i & 31;
            cp16(dbase + (uint32_t)(W_BUF + n * SWC) * 4 + (uint32_t)q * 16,
                 s1 + i);
        }
        const uint4* s3 = (const uint4*)g_L2C;
        for (int i = t; i < 512; i += 256) {
            const int n = i >> 5, q = i & 31;
            cp16(dbase + (uint32_t)(W_B3 + n * SWC) * 4 + (uint32_t)q * 16,
                 s3 + i);
        }
        CP_COMMIT();
    }

    if (t < 128) {
        idxs[t] = swr[f * NEST + t];
        pg1[t] = ln1g[t]; pb1[t] = ln1b[t];
        plb[t] = lin1b[t];
        pg2[t] = ln2g[t]; pb2[t] = ln2b[t];
    }
    if (t < 16) pl2b[t] = (t < NCLASS) ? lin2b[t] : 0.f;
    __syncthreads();   // idxs visible for gather

    // ---- gather A1 fragments DIRECTLY into registers + row sums ----
    uint32_t Ah[16], Al[16], Bh[16], Bl[16];   // rows rA / rA+8, word slots
    float SA, SB;
    {
        const int rA = b0 + mbase + g;     // global batch row (and rA+8)
        float sA = 0.f, sB = 0.f;
#pragma unroll
        for (int ks = 0; ks < 8; ks++) {
            const int kw = ks * 8 + tg;
            const float* p0 = g_EWT + (size_t)idxs[2 * kw]     * BATCH + rA;
            const float* p1 = g_EWT + (size_t)idxs[2 * kw + 1] * BATCH + rA;
            const float* p2 = g_EWT + (size_t)idxs[2 * kw + 8] * BATCH + rA;
            const float* p3 = g_EWT + (size_t)idxs[2 * kw + 9] * BATCH + rA;
            const float a0 = p0[0], a0b = p0[8];
            const float a1 = p1[0], a1b = p1[8];
            const float a2 = p2[0], a2b = p2[8];
            const float a3 = p3[0], a3b = p3[8];
            sA += a0 + a1 + a2 + a3;
            sB += a0b + a1b + a2b + a3b;
            split2(a0, a1, Ah[2 * ks],     Al[2 * ks]);
            split2(a2, a3, Ah[2 * ks + 1], Al[2 * ks + 1]);
            split2(a0b, a1b, Bh[2 * ks],     Bl[2 * ks]);
            split2(a2b, a3b, Bh[2 * ks + 1], Bl[2 * ks + 1]);
        }
        sA += __shfl_xor_sync(0xffffffffu, sA, 1);
        sA += __shfl_xor_sync(0xffffffffu, sA, 2);
        sB += __shfl_xor_sync(0xffffffffu, sB, 1);
        sB += __shfl_xor_sync(0xffffffffu, sB, 2);
        SA = sA; SB = sB;
    }
    CP_WAIT(0);        // B1 + B3 landed
    __syncthreads();

    // =============== GEMM1: D = A1 @ B1 (Es, in shared buffer) ===============
    float C[16][4];
#pragma unroll
    for (int nt = 0; nt < 16; nt++)
#pragma unroll
        for (int j = 0; j < 4; j++) C[nt][j] = 0.f;

#pragma unroll
    for (int ks = 0; ks < 8; ks++) {
        const uint32_t ah0 = Ah[2 * ks],     ah1 = Bh[2 * ks];
        const uint32_t ah2 = Ah[2 * ks + 1], ah3 = Bh[2 * ks + 1];
        const uint32_t al0 = Al[2 * ks],     al1 = Bl[2 * ks];
        const uint32_t al2 = Al[2 * ks + 1], al3 = Bl[2 * ks + 1];
#pragma unroll
        for (int nt = 0; nt < 16; nt++) {
            const uint4 q = *(const uint4*)(sw4 + W_BUF + (nt * 8 + g) * SWC
                                            + ks * 16 + tg * 4);
            mma_bf16(C[nt], ah0, ah1, ah2, ah3, q.x, q.y);
            mma_bf16(C[nt], ah0, ah1, ah2, ah3, q.z, q.w);
            mma_bf16(C[nt], al0, al1, al2, al3, q.x, q.y);
        }
    }

    // ---- epilogue 1: /S, LN1 -> refill A fragment registers ----
    {
        const float iA = 1.f / SA, iB = 1.f / SB;
        float sA = 0.f, qA = 0.f, sB = 0.f, qB = 0.f;
#pragma unroll
        for (int nt = 0; nt < 16; nt++) {
            C[nt][0] *= iA; C[nt][1] *= iA;
            C[nt][2] *= iB; C[nt][3] *= iB;
            sA += C[nt][0] + C[nt][1];
            qA += C[nt][0] * C[nt][0] + C[nt][1] * C[nt][1];
            sB += C[nt][2] + C[nt][3];
            qB += C[nt][2] * C[nt][2] + C[nt][3] * C[nt][3];
        }
#pragma unroll
        for (int o = 1; o <= 2; o <<= 1) {
            sA += __shfl_xor_sync(0xffffffffu, sA, o);
            qA += __shfl_xor_sync(0xffffffffu, qA, o);
            sB += __shfl_xor_sync(0xffffffffu, sB, o);
            qB += __shfl_xor_sync(0xffffffffu, qB, o);
        }
        const float mA = sA * (1.f / NHID);
        const float rA = rsqrtf(qA * (1.f / NHID) - mA * mA + EPSF);
        const float mB = sB * (1.f / NHID);
        const float rB = rsqrtf(qB * (1.f / NHID) - mB * mB + EPSF);
#pragma unroll
        for (int nt = 0; nt < 16; nt++) {
            const int n0 = nt * 8 + tg * 2, n1 = n0 + 1;
            const float zA0 = (C[nt][0] - mA) * rA * pg1[n0] + pb1[n0];
            const float zA1 = (C[nt][1] - mA) * rA * pg1[n1] + pb1[n1];
            const float zB0 = (C[nt][2] - mB) * rB * pg1[n0] + pb1[n0];
            const float zB1 = (C[nt][3] - mB) * rB * pg1[n1] + pb1[n1];
            split2(zA0, zA1, Ah[nt], Al[nt]);
            split2(zB0, zB1, Bh[nt], Bl[nt]);
        }
    }
    __syncthreads();   // ALL warps done reading B1 before overwrite

    // ---- load B2 (lin1w) into the same buffer ----
    {
        const uint4* s2 = (const uint4*)g_L1C;
        for (int i = t; i < 4096; i += 256) {
            const int n = i >> 5, q = i & 31;
            cp16(dbase + (uint32_t)(W_BUF + n * SWC) * 4 + (uint32_t)q * 16,
                 s2 + i);
        }
        CP_COMMIT();
    }
    CP_WAIT(0);
    __syncthreads();

    // =============== GEMM2: D = z1 @ lin1w (A from registers) ===============
#pragma unroll
    for (int nt = 0; nt < 16; nt++)
#pragma unroll
        for (int j = 0; j < 4; j++) C[nt][j] = 0.f;

#pragma unroll
    for (int ks = 0; ks < 8; ks++) {
        const uint32_t ah0 = Ah[2 * ks],     ah1 = Bh[2 * ks];
        const uint32_t ah2 = Ah[2 * ks + 1], ah3 = Bh[2 * ks + 1];
        const uint32_t al0 = Al[2 * ks],     al1 = Bl[2 * ks];
        const uint32_t al2 = Al[2 * ks + 1], al3 = Bl[2 * ks + 1];
#pragma unroll
        for (int nt = 0; nt < 16; nt++) {
            const uint4 q = *(const uint4*)(sw4 + W_BUF + (nt * 8 + g) * SWC
                                            + ks * 16 + tg * 4);
            mma_bf16(C[nt], ah0, ah1, ah2, ah3, q.x, q.y);
            mma_bf16(C[nt], ah0, ah1, ah2, ah3, q.z, q.w);
            mma_bf16(C[nt], al0, al1, al2, al3, q.x, q.y);
        }
    }

    // ---- epilogue 2: +bias, ReLU, LN2 -> A fragment registers ----
    {
        float sA = 0.f, qA = 0.f, sB = 0.f, qB = 0.f;
#pragma unroll
        for (int nt = 0; nt < 16; nt++) {
            const int n0 = nt * 8 + tg * 2, n1 = n0 + 1;
            C[nt][0] = fmaxf(C[nt][0] + plb[n0], 0.f);
            C[nt][1] = fmaxf(C[nt][1] + plb[n1], 0.f);
            C[nt][2] = fmaxf(C[nt][2] + plb[n0], 0.f);
            C[nt][3] = fmaxf(C[nt][3] + plb[n1], 0.f);
            sA += C[nt][0] + C[nt][1];
            qA += C[nt][0] * C[nt][0] + C[nt][1] * C[nt][1];
            sB += C[nt][2] + C[nt][3];
            qB += C[nt][2] * C[nt][2] + C[nt][3] * C[nt][3];
        }
#pragma unroll
        for (int o = 1; o <= 2; o <<= 1) {
            sA += __shfl_xor_sync(0xffffffffu, sA, o);
            qA += __shfl_xor_sync(0xffffffffu, qA, o);
            sB += __shfl_xor_sync(0xffffffffu, sB, o);
            qB += __shfl_xor_sync(0xffffffffu, qB, o);
        }
        const float mA = sA * (1.f / NHID);
        const float rA = rsqrtf(qA * (1.f / NHID) - mA * mA + EPSF);
        const float mB = sB * (1.f / NHID);
        const float rB = rsqrtf(qB * (1.f / NHID) - mB * mB + EPSF);
#pragma unroll
        for (int nt = 0; nt < 16; nt++) {
            const int n0 = nt * 8 + tg * 2, n1 = n0 + 1;
            const float zA0 = (C[nt][0] - mA) * rA * pg2[n0] + pb2[n0];
            const float zA1 = (C[nt][1] - mA) * rA * pg2[n1] + pb2[n1];
            const float zB0 = (C[nt][2] - mB) * rB * pg2[n0] + pb2[n0];
            const float zB1 = (C[nt][3] - mB) * rB * pg2[n1] + pb2[n1];
            split2(zA0, zA1, Ah[nt], Al[nt]);
            split2(zB0, zB1, Bh[nt], Bl[nt]);
        }
    }

    // =============== GEMM3: logits = z2 @ lin2w (N=16 padded) ===============
    float Y[2][4];
#pragma unroll
    for (int nt = 0; nt < 2; nt++)
#pragma unroll
        for (int j = 0; j < 4; j++) Y[nt][j] = 0.f;

#pragma unroll
    for (int ks = 0; ks < 8; ks++) {
        const uint32_t ah0 = Ah[2 * ks],     ah1 = Bh[2 * ks];
        const uint32_t ah2 = Ah[2 * ks + 1], ah3 = Bh[2 * ks + 1];
        const uint32_t al0 = Al[2 * ks],     al1 = Bl[2 * ks];
        const uint32_t al2 = Al[2 * ks + 1], al3 = Bl[2 * ks + 1];
#pragma unroll
        for (int nt = 0; nt < 2; nt++) {
            const uint4 q = *(const uint4*)(sw4 + W_B3 + (nt * 8 + g) * SWC
                                            + ks * 16 + tg * 4);
            mma_bf16(Y[nt], ah0, ah1, ah2, ah3, q.x, q.y);
            mma_bf16(Y[nt], ah0, ah1, ah2, ah3, q.z, q.w);
            mma_bf16(Y[nt], al0, al1, al2, al3, q.x, q.y);
        }
    }

    // ---- write logits ----
    {
        float* yA = g_Y + ((size_t)f * BATCH + b0 + mbase + g) * NCLASS;
        float* yB = g_Y + ((size_t)f * BATCH + b0 + mbase + g + 8) * NCLASS;
#pragma unroll
        for (int nt = 0; nt < 2; nt++) {
            const int n0 = nt * 8 + tg * 2, n1 = n0 + 1;
            if (n0 < NCLASS) {
                yA[n0] = Y[nt][0] + pl2b[n0];
                yB[n0] = Y[nt][2] + pl2b[n0];
            }
            if (n1 < NCLASS) {
                yA[n1] = Y[nt][1] + pl2b[n1];
                yB[n1] = Y[nt][3] + pl2b[n1];
            }
        }
    }
}

// ---------------------------------------------------------------------------
// Kernel 3: mean over forests, 4-way f-split per block
// ---------------------------------------------------------------------------
__global__ void mean_kernel(float* __restrict__ out)
{
    __shared__ float part[4][64];
    const int t = threadIdx.x;
    const int i = blockIdx.x * 64 + (t & 63);
    const int fg = t >> 6;
    float s = 0.f;
#pragma unroll 5
    for (int f = fg * 25; f < fg * 25 + 25; f++)
        s += g_Y[(size_t)f * (BATCH * NCLASS) + i];
    part[fg][t & 63] = s;
    __syncthreads();
    if (t < 64)
        out[blockIdx.x * 64 + t] =
            (part[0][t] + part[1][t] + part[2][t] + part[3][t]) * (1.f / NFOREST);
}

// ---------------------------------------------------------------------------
extern "C" void kernel_launch(void* const* d_in, const int* in_sizes, int n_in,
                              void* d_out, int out_size)
{
    const float* x     = (const float*)d_in[0];
    const float* w1    = (const float*)d_in[1];
    const float* b1    = (const float*)d_in[2];
    const int*   perm  = (const int*)  d_in[3];
    const float* gn1g  = (const float*)d_in[4];
    const float* gn1b  = (const float*)d_in[5];
    const float* w2a   = (const float*)d_in[6];
    const float* b2a   = (const float*)d_in[7];
    const float* gn2g  = (const float*)d_in[8];
    const float* gn2b  = (const float*)d_in[9];
    const float* w2b   = (const float*)d_in[10];
    const float* b2b   = (const float*)d_in[11];
    const float* E     = (const float*)d_in[12];
    const int*   swr   = (const int*)  d_in[13];
    const float* ln1g  = (const float*)d_in[14];
    const float* ln1b  = (const float*)d_in[15];
    const float* lin1w = (const float*)d_in[16];
    const float* lin1b = (const float*)d_in[17];
    const float* ln2g  = (const float*)d_in[18];
    const float* ln2b  = (const float*)d_in[19];
    const float* lin2w = (const float*)d_in[20];
    const float* lin2b = (const float*)d_in[21];

    const int dyn_smem = SMEM_WORDS * 4;   // 82,944 B -> 2 blocks/SM
    cudaFuncSetAttribute(forest_mma,
                         cudaFuncAttributeMaxDynamicSharedMemorySize, dyn_smem);

    cond_kernel<<<dim3(NRODT / 256, BATCH / CB), 256>>>(
        x, w1, b1, perm, gn1g, gn1b, w2a, b2a, gn2g, gn2b, w2b, b2b);
    rowmax_kernel<<<BATCH / 8, 256>>>();
    expT_kernel<<<dim3(NRODT / 32, BATCH / 32), dim3(32, 8)>>>();
    prep_es<<<dim3(NFOREST, 16), 128>>>(E, swr);
    prep_l1<<<8, 128>>>(lin1w);
    prep_l2<<<16, 32>>>(lin2w);

    forest_mma<<<dim3(BATCH / 128, NFOREST), 256, dyn_smem>>>(
        swr, ln1g, ln1b, lin1b, ln2g, ln2b, lin2b);

    mean_kernel<<<BATCH * NCLASS / 64, 256>>>((float*)d_out);
}

// round 17
// speedup vs baseline: 1.1008x; 1.0552x over previous
#include <cuda_runtime.h>
#include <cuda_bf16.h>
#include <cstdint>

#define BATCH   1024
#define NCOL    64
#define NCOND   64
#define NRODT   1024
#define NEST    128
#define NFOREST 100
#define NHID    128
#define NCLASS  10
#define EPSF    1e-5f
#define CB      16          // batch rows per cond block

// smem layout: ONE shared B buffer (B1 then B2), 144-word rows
// (stride ≡ 16 mod 32 -> conflict-free LDS.128), plus small B3 tile.
#define SWC   144
#define W_BUF 0
#define W_B3  18432         // 128*144
#define SMEM_WORDS 20736    // 82,944 bytes -> 2 blocks/SM

// ---------------- scratch ---------------------------------------------------
__device__ float g_W  [BATCH * NRODT];
__device__ float g_EWT[NRODT * BATCH];            // exp(w), TRANSPOSED [g][b]
__device__ float g_Y  [(size_t)NFOREST * BATCH * NCLASS];
__device__ uint32_t g_EsC[NFOREST * 16384];       // B1 combined [n][128w] per forest
__device__ uint32_t g_L1C[16384];                 // B2 combined
__device__ uint32_t g_L2C[2048];                  // B3 combined (16 rows x 128w)

// ---------------- helpers ----------------------------------------------------
__device__ __forceinline__ uint32_t pack_bf16(float a, float b) {
    __nv_bfloat16 ha = __float2bfloat16(a), hb = __float2bfloat16(b);
    return (uint32_t)__bfloat16_as_ushort(ha)
         | ((uint32_t)__bfloat16_as_ushort(hb) << 16);
}
__device__ __forceinline__ void split2(float a, float b,
                                       uint32_t& hi, uint32_t& lo) {
    __nv_bfloat16 ha = __float2bfloat16(a), hb = __float2bfloat16(b);
    float ra = a - __bfloat162float(ha);
    float rb = b - __bfloat162float(hb);
    hi = (uint32_t)__bfloat16_as_ushort(ha)
       | ((uint32_t)__bfloat16_as_ushort(hb) << 16);
    lo = pack_bf16(ra, rb);
}
__device__ __forceinline__ void mma_bf16(float* c,
    uint32_t a0, uint32_t a1, uint32_t a2, uint32_t a3,
    uint32_t b0, uint32_t b1) {
    asm volatile(
        "mma.sync.aligned.m16n8k16.row.col.f32.bf16.bf16.f32 "
        "{%0,%1,%2,%3},{%4,%5,%6,%7},{%8,%9},{%0,%1,%2,%3};"
        : "+f"(c[0]), "+f"(c[1]), "+f"(c[2]), "+f"(c[3])
        : "r"(a0), "r"(a1), "r"(a2), "r"(a3), "r"(b0), "r"(b1));
}
__device__ __forceinline__ float fast_sigmoid(float x) {
    float th;
    asm("tanh.approx.f32 %0, %1;" : "=f"(th) : "f"(x * 0.5f));
    return fmaf(0.5f, th, 0.5f);
}
__device__ __forceinline__ uint32_t smem_u32(const void* p) {
    uint32_t a;
    asm("{ .reg .u64 t; cvta.to.shared.u64 t, %1; cvt.u32.u64 %0, t; }"
        : "=r"(a) : "l"(p));
    return a;
}
__device__ __forceinline__ void cp16(uint32_t dst, const void* src) {
    asm volatile("cp.async.cg.shared.global [%0], [%1], 16;"
                 :: "r"(dst), "l"(src));
}
#define CP_COMMIT() asm volatile("cp.async.commit_group;" ::: "memory")
#define CP_WAIT(n)  asm volatile("cp.async.wait_group %0;" :: "n"(n) : "memory")

// ---------------------------------------------------------------------------
// Kernel 1: condition generation, 16 batch rows per block (param reuse)
// ---------------------------------------------------------------------------
__global__ void __launch_bounds__(256) cond_kernel(
    const float* __restrict__ x,    const float* __restrict__ w1,
    const float* __restrict__ b1,   const int*   __restrict__ perm,
    const float* __restrict__ gn1g, const float* __restrict__ gn1b,
    const float* __restrict__ w2a,  const float* __restrict__ b2a,
    const float* __restrict__ gn2g, const float* __restrict__ gn2b,
    const float* __restrict__ w2b,  const float* __restrict__ b2b)
{
    __shared__ float xs[CB][NCOL];
    const int t  = threadIdx.x;
    const int g  = blockIdx.x * 256 + t;
    const int b0 = blockIdx.y * CB;

    ((float4*)&xs[0][0])[t] = ((const float4*)(x + b0 * NCOL))[t];

    const int4 p4 = ((const int4*)perm)[g];
    const int pv[4] = {p4.x, p4.y, p4.z, p4.w};
    float w1v[4], b1v[4];
    int   col[4];
#pragma unroll
    for (int i = 0; i < 4; i++) {
        col[i] = pv[i] & 63;
        const int wi = col[i] * NCOND + (pv[i] >> 6);
        w1v[i] = w1[wi]; b1v[i] = b1[wi];
    }
    const float4 g1  = ((const float4*)gn1g)[g];
    const float4 be1 = ((const float4*)gn1b)[g];
    const float4 bb2 = ((const float4*)b2a)[g];
    const float4 wr0 = ((const float4*)w2a)[g * 4 + 0];
    const float4 wr1 = ((const float4*)w2a)[g * 4 + 1];
    const float4 wr2 = ((const float4*)w2a)[g * 4 + 2];
    const float4 wr3 = ((const float4*)w2a)[g * 4 + 3];
    const float4 g2  = ((const float4*)gn2g)[g];
    const float4 be2 = ((const float4*)gn2b)[g];
    const float4 wb  = ((const float4*)w2b)[g];
    const float bb   = b2b[g];
    __syncthreads();

#pragma unroll 2
    for (int r = 0; r < CB; r++) {
        float o[4];
#pragma unroll
        for (int i = 0; i < 4; i++)
            o[i] = fast_sigmoid(fmaf(xs[r][col[i]], w1v[i], b1v[i]));

        float mu = 0.f, s2 = 0.f;
#pragma unroll
        for (int i = 0; i < 4; i++) { mu += o[i]; s2 += o[i] * o[i]; }
        mu *= 0.25f; s2 = s2 * 0.25f - mu * mu;
        const float rstd = rsqrtf(s2 + EPSF);
        float hn[4];
        hn[0] = (o[0] - mu) * rstd * g1.x + be1.x;
        hn[1] = (o[1] - mu) * rstd * g1.y + be1.y;
        hn[2] = (o[2] - mu) * rstd * g1.z + be1.z;
        hn[3] = (o[3] - mu) * rstd * g1.w + be1.w;

        float h2[4] = {bb2.x, bb2.y, bb2.z, bb2.w};
        h2[0] = fmaf(hn[0], wr0.x, h2[0]); h2[1] = fmaf(hn[0], wr0.y, h2[1]);
        h2[2] = fmaf(hn[0], wr0.z, h2[2]); h2[3] = fmaf(hn[0], wr0.w, h2[3]);
        h2[0] = fmaf(hn[1], wr1.x, h2[0]); h2[1] = fmaf(hn[1], wr1.y, h2[1]);
        h2[2] = fmaf(hn[1], wr1.z, h2[2]); h2[3] = fmaf(hn[1], wr1.w, h2[3]);
        h2[0] = fmaf(hn[2], wr2.x, h2[0]); h2[1] = fmaf(hn[2], wr2.y, h2[1]);
        h2[2] = fmaf(hn[2], wr2.z, h2[2]); h2[3] = fmaf(hn[2], wr2.w, h2[3]);
        h2[0] = fmaf(hn[3], wr3.x, h2[0]); h2[1] = fmaf(hn[3], wr3.y, h2[1]);
        h2[2] = fmaf(hn[3], wr3.z, h2[2]); h2[3] = fmaf(hn[3], wr3.w, h2[3]);
#pragma unroll
        for (int i = 0; i < 4; i++) h2[i] = fmaxf(h2[i], 0.f);

        float mu2 = 0.f, t2 = 0.f;
#pragma unroll
        for (int i = 0; i < 4; i++) { mu2 += h2[i]; t2 += h2[i] * h2[i]; }
        mu2 *= 0.25f; t2 = t2 * 0.25f - mu2 * mu2;
        const float rstd2 = rsqrtf(t2 + EPSF);
        float wv = bb;
        wv = fmaf((h2[0] - mu2) * rstd2 * g2.x + be2.x, wb.x, wv);
        wv = fmaf((h2[1] - mu2) * rstd2 * g2.y + be2.y, wb.y, wv);
        wv = fmaf((h2[2] - mu2) * rstd2 * g2.z + be2.z, wb.z, wv);
        wv = fmaf((h2[3] - mu2) * rstd2 * g2.w + be2.w, wb.w, wv);
        g_W[(b0 + r) * NRODT + g] = wv;
    }
}

// ---------------------------------------------------------------------------
// exp + transpose: g_EWT[g][b] = exp(g_W[b][g]).
// No max subtraction: softmax is shift-invariant and |w| << 88 here
// (unit-normalized activations dotted with 0.1-scale weights).
// ---------------------------------------------------------------------------
__global__ void expT_kernel()
{
    __shared__ float tile[32][33];
    const int bx = blockIdx.x * 32, by = blockIdx.y * 32;
    const int tx = threadIdx.x, ty = threadIdx.y;   // 32 x 8
#pragma unroll
    for (int j = 0; j < 32; j += 8) {
        const int b = by + ty + j;
        tile[ty + j][tx] = __expf(g_W[b * NRODT + bx + tx]);
    }
    __syncthreads();
#pragma unroll
    for (int j = 0; j < 32; j += 8)
        g_EWT[(bx + ty + j) * BATCH + by + tx] = tile[tx][ty + j];
}

// ---------------------------------------------------------------------------
// Prep: build combined B tiles. Per (row n, cell(ks,tg)): one uint4 store
// {hi(kw), hi(kw+4), lo(kw), lo(kw+4)},  kw = ks*8+tg.
// ---------------------------------------------------------------------------
__global__ void prep_es(const float* __restrict__ E, const int* __restrict__ swr)
{
    __shared__ int idx[NEST];
    const int f = blockIdx.x;
    const int t = threadIdx.x;            // row n = hidden channel
    if (t < NEST) idx[t] = swr[f * NEST + t];
    __syncthreads();
    uint32_t* rowP = g_EsC + f * 16384 + t * 128;
#pragma unroll
    for (int c = 0; c < 2; c++) {
        const int cell = blockIdx.y * 2 + c;       // 0..31
        const int ks = cell >> 2, tg = cell & 3;
        const int kw = ks * 8 + tg;
        const float v0 = __ldg(&E[(size_t)idx[2 * kw]     * NHID + t]);
        const float v1 = __ldg(&E[(size_t)idx[2 * kw + 1] * NHID + t]);
        const float v2 = __ldg(&E[(size_t)idx[2 * kw + 8] * NHID + t]);
        const float v3 = __ldg(&E[(size_t)idx[2 * kw + 9] * NHID + t]);
        uint32_t ha, la, hb, lb;
        split2(v0, v1, ha, la);
        split2(v2, v3, hb, lb);
        *(uint4*)(rowP + ks * 16 + tg * 4) = make_uint4(ha, hb, la, lb);
    }
}
// merged lin1w / lin2w prep: blocks 0..31 -> L1 cell, blocks 32..47 -> L2 row
__global__ void prep_lw(const float* __restrict__ lin1w,
                        const float* __restrict__ lin2w)
{
    const int t = threadIdx.x;            // 128 threads
    if (blockIdx.x < 32) {
        const int cell = blockIdx.x;      // L1: row n = t
        const int ks = cell >> 2, tg = cell & 3;
        const int kw = ks * 8 + tg;
        const float v0 = lin1w[(2 * kw) * NHID + t];
        const float v1 = lin1w[(2 * kw + 1) * NHID + t];
        const float v2 = lin1w[(2 * kw + 8) * NHID + t];
        const float v3 = lin1w[(2 * kw + 9) * NHID + t];
        uint32_t ha, la, hb, lb;
        split2(v0, v1, ha, la);
        split2(v2, v3, hb, lb);
        *(uint4*)(g_L1C + t * 128 + ks * 16 + tg * 4) = make_uint4(ha, hb, la, lb);
    } else if (t < 32) {
        const int n = blockIdx.x - 32;    // 0..15 (padded class)
        const int cell = t;
        const int ks = cell >> 2, tg = cell & 3;
        const int kw = ks * 8 + tg;
        const bool ok = (n < NCLASS);
        const float v0 = ok ? lin2w[(2 * kw) * NCLASS + n] : 0.f;
        const float v1 = ok ? lin2w[(2 * kw + 1) * NCLASS + n] : 0.f;
        const float v2 = ok ? lin2w[(2 * kw + 8) * NCLASS + n] : 0.f;
        const float v3 = ok ? lin2w[(2 * kw + 9) * NCLASS + n] : 0.f;
        uint32_t ha, la, hb, lb;
        split2(v0, v1, ha, la);
        split2(v2, v3, hb, lb);
        *(uint4*)(g_L2C + n * 128 + ks * 16 + tg * 4) = make_uint4(ha, hb, la, lb);
    }
}

// ---------------------------------------------------------------------------
// Kernel 2: HMMA forest kernel.  Block = (128-row tile, forest f), 8 warps,
// 2 blocks/SM.  B1 and B2 share one smem buffer (B2 loaded after GEMM1).
// A fragments fully register-resident.  (Exact R11 configuration.)
// ---------------------------------------------------------------------------
__global__ void __launch_bounds__(256, 2) forest_mma(
    const int*   __restrict__ swr,
    const float* __restrict__ ln1g, const float* __restrict__ ln1b,
    const float* __restrict__ lin1b,
    const float* __restrict__ ln2g, const float* __restrict__ ln2b,
    const float* __restrict__ lin2b)
{
    extern __shared__ __align__(16) uint32_t sw4[];
    __shared__ float pg1[128], pb1[128], plb[128], pg2[128], pb2[128];
    __shared__ float pl2b[16];
    __shared__ int idxs[NEST];

    const int t = threadIdx.x;
    const int f = blockIdx.y;
    const int b0 = blockIdx.x * 128;
    const int w = t >> 5, lane = t & 31, g = lane >> 2, tg = lane & 3;
    const int mbase = w * 16;
    const uint32_t dbase = smem_u32(sw4);

    // ---- async copies: B1 (Es) into shared buffer, B3 small tile ----
    {
        const uint4* s1 = (const uint4*)(g_EsC + f * 16384);
        for (int i = t; i < 4096; i += 256) {
            const int n = i >> 5, q = i & 31;
            cp16(dbase + (uint32_t)(W_BUF + n * SWC) * 4 + (uint32_t)q * 16,
                 s1 + i);
        }
        const uint4* s3 = (const uint4*)g_L2C;
        for (int i = t; i < 512; i += 256) {
            const int n = i >> 5, q = i & 31;
            cp16(dbase + (uint32_t)(W_B3 + n * SWC) * 4 + (uint32_t)q * 16,
                 s3 + i);
        }
        CP_COMMIT();
    }

    if (t < 128) {
        idxs[t] = swr[f * NEST + t];
        pg1[t] = ln1g[t]; pb1[t] = ln1b[t];
        plb[t] = lin1b[t];
        pg2[t] = ln2g[t]; pb2[t] = ln2b[t];
    }
    if (t < 16) pl2b[t] = (t < NCLASS) ? lin2b[t] : 0.f;
    __syncthreads();   // idxs visible for gather

    // ---- gather A1 fragments DIRECTLY into registers + row sums ----
    uint32_t Ah[16], Al[16], Bh[16], Bl[16];   // rows rA / rA+8, word slots
    float SA, SB;
    {
        const int rA = b0 + mbase + g;     // global batch row (and rA+8)
        float sA = 0.f, sB = 0.f;
#pragma unroll
        for (int ks = 0; ks < 8; ks++) {
            const int kw = ks * 8 + tg;
            const float* p0 = g_EWT + (size_t)idxs[2 * kw]     * BATCH + rA;
            const float* p1 = g_EWT + (size_t)idxs[2 * kw + 1] * BATCH + rA;
            const float* p2 = g_EWT + (size_t)idxs[2 * kw + 8] * BATCH + rA;
            const float* p3 = g_EWT + (size_t)idxs[2 * kw + 9] * BATCH + rA;
            const float a0 = p0[0], a0b = p0[8];
            const float a1 = p1[0], a1b = p1[8];
            const float a2 = p2[0], a2b = p2[8];
            const float a3 = p3[0], a3b = p3[8];
            sA += a0 + a1 + a2 + a3;
            sB += a0b + a1b + a2b + a3b;
            split2(a0, a1, Ah[2 * ks],     Al[2 * ks]);
            split2(a2, a3, Ah[2 * ks + 1], Al[2 * ks + 1]);
            split2(a0b, a1b, Bh[2 * ks],     Bl[2 * ks]);
            split2(a2b, a3b, Bh[2 * ks + 1], Bl[2 * ks + 1]);
        }
        sA += __shfl_xor_sync(0xffffffffu, sA, 1);
        sA += __shfl_xor_sync(0xffffffffu, sA, 2);
        sB += __shfl_xor_sync(0xffffffffu, sB, 1);
        sB += __shfl_xor_sync(0xffffffffu, sB, 2);
        SA = sA; SB = sB;
    }
    CP_WAIT(0);        // B1 + B3 landed
    __syncthreads();

    // =============== GEMM1: D = A1 @ B1 (Es, in shared buffer) ===============
    float C[16][4];
#pragma unroll
    for (int nt = 0; nt < 16; nt++)
#pragma unroll
        for (int j = 0; j < 4; j++) C[nt][j] = 0.f;

#pragma unroll
    for (int ks = 0; ks < 8; ks++) {
        const uint32_t ah0 = Ah[2 * ks],     ah1 = Bh[2 * ks];
        const uint32_t ah2 = Ah[2 * ks + 1], ah3 = Bh[2 * ks + 1];
        const uint32_t al0 = Al[2 * ks],     al1 = Bl[2 * ks];
        const uint32_t al2 = Al[2 * ks + 1], al3 = Bl[2 * ks + 1];
#pragma unroll
        for (int nt = 0; nt < 16; nt++) {
            const uint4 q = *(const uint4*)(sw4 + W_BUF + (nt * 8 + g) * SWC
                                            + ks * 16 + tg * 4);
            mma_bf16(C[nt], ah0, ah1, ah2, ah3, q.x, q.y);
            mma_bf16(C[nt], ah0, ah1, ah2, ah3, q.z, q.w);
            mma_bf16(C[nt], al0, al1, al2, al3, q.x, q.y);
        }
    }

    // ---- epilogue 1: /S, LN1 -> refill A fragment registers ----
    {
        const float iA = 1.f / SA, iB = 1.f / SB;
        float sA = 0.f, qA = 0.f, sB = 0.f, qB = 0.f;
#pragma unroll
        for (int nt = 0; nt < 16; nt++) {
            C[nt][0] *= iA; C[nt][1] *= iA;
            C[nt][2] *= iB; C[nt][3] *= iB;
            sA += C[nt][0] + C[nt][1];
            qA += C[nt][0] * C[nt][0] + C[nt][1] * C[nt][1];
            sB += C[nt][2] + C[nt][3];
            qB += C[nt][2] * C[nt][2] + C[nt][3] * C[nt][3];
        }
#pragma unroll
        for (int o = 1; o <= 2; o <<= 1) {
            sA += __shfl_xor_sync(0xffffffffu, sA, o);
            qA += __shfl_xor_sync(0xffffffffu, qA, o);
            sB += __shfl_xor_sync(0xffffffffu, sB, o);
            qB += __shfl_xor_sync(0xffffffffu, qB, o);
        }
        const float mA = sA * (1.f / NHID);
        const float rA = rsqrtf(qA * (1.f / NHID) - mA * mA + EPSF);
        const float mB = sB * (1.f / NHID);
        const float rB = rsqrtf(qB * (1.f / NHID) - mB * mB + EPSF);
#pragma unroll
        for (int nt = 0; nt < 16; nt++) {
            const int n0 = nt * 8 + tg * 2, n1 = n0 + 1;
            const float zA0 = (C[nt][0] - mA) * rA * pg1[n0] + pb1[n0];
            const float zA1 = (C[nt][1] - mA) * rA * pg1[n1] + pb1[n1];
            const float zB0 = (C[nt][2] - mB) * rB * pg1[n0] + pb1[n0];
            const float zB1 = (C[nt][3] - mB) * rB * pg1[n1] + pb1[n1];
            split2(zA0, zA1, Ah[nt], Al[nt]);
            split2(zB0, zB1, Bh[nt], Bl[nt]);
        }
    }
    __syncthreads();   // ALL warps done reading B1 before overwrite

    // ---- load B2 (lin1w) into the same buffer ----
    {
        const uint4* s2 = (const uint4*)g_L1C;
        for (int i = t; i < 4096; i += 256) {
            const int n = i >> 5, q = i & 31;
            cp16(dbase + (uint32_t)(W_BUF + n * SWC) * 4 + (uint32_t)q * 16,
                 s2 + i);
        }
        CP_COMMIT();
    }
    CP_WAIT(0);
    __syncthreads();

    // =============== GEMM2: D = z1 @ lin1w (A from registers) ===============
#pragma unroll
    for (int nt = 0; nt < 16; nt++)
#pragma unroll
        for (int j = 0; j < 4; j++) C[nt][j] = 0.f;

#pragma unroll
    for (int ks = 0; ks < 8; ks++) {
        const uint32_t ah0 = Ah[2 * ks],     ah1 = Bh[2 * ks];
        const uint32_t ah2 = Ah[2 * ks + 1], ah3 = Bh[2 * ks + 1];
        const uint32_t al0 = Al[2 * ks],     al1 = Bl[2 * ks];
        const uint32_t al2 = Al[2 * ks + 1], al3 = Bl[2 * ks + 1];
#pragma unroll
        for (int nt = 0; nt < 16; nt++) {
            const uint4 q = *(const uint4*)(sw4 + W_BUF + (nt * 8 + g) * SWC
                                            + ks * 16 + tg * 4);
            mma_bf16(C[nt], ah0, ah1, ah2, ah3, q.x, q.y);
            mma_bf16(C[nt], ah0, ah1, ah2, ah3, q.z, q.w);
            mma_bf16(C[nt], al0, al1, al2, al3, q.x, q.y);
        }
    }

    // ---- epilogue 2: +bias, ReLU, LN2 -> A fragment registers ----
    {
        float sA = 0.f, qA = 0.f, sB = 0.f, qB = 0.f;
#pragma unroll
        for (int nt = 0; nt < 16; nt++) {
            const int n0 = nt * 8 + tg * 2, n1 = n0 + 1;
            C[nt][0] = fmaxf(C[nt][0] + plb[n0], 0.f);
            C[nt][1] = fmaxf(C[nt][1] + plb[n1], 0.f);
            C[nt][2] = fmaxf(C[nt][2] + plb[n0], 0.f);
            C[nt][3] = fmaxf(C[nt][3] + plb[n1], 0.f);
            sA += C[nt][0] + C[nt][1];
            qA += C[nt][0] * C[nt][0] + C[nt][1] * C[nt][1];
            sB += C[nt][2] + C[nt][3];
            qB += C[nt][2] * C[nt][2] + C[nt][3] * C[nt][3];
        }
#pragma unroll
        for (int o = 1; o <= 2; o <<= 1) {
            sA += __shfl_xor_sync(0xffffffffu, sA, o);
            qA += __shfl_xor_sync(0xffffffffu, qA, o);
            sB += __shfl_xor_sync(0xffffffffu, sB, o);
            qB += __shfl_xor_sync(0xffffffffu, qB, o);
        }
        const float mA = sA * (1.f / NHID);
        const float rA = rsqrtf(qA * (1.f / NHID) - mA * mA + EPSF);
        const float mB = sB * (1.f / NHID);
        const float rB = rsqrtf(qB * (1.f / NHID) - mB * mB + EPSF);
#pragma unroll
        for (int nt = 0; nt < 16; nt++) {
            const int n0 = nt * 8 + tg * 2, n1 = n0 + 1;
            const float zA0 = (C[nt][0] - mA) * rA * pg2[n0] + pb2[n0];
            const float zA1 = (C[nt][1] - mA) * rA * pg2[n1] + pb2[n1];
            const float zB0 = (C[nt][2] - mB) * rB * pg2[n0] + pb2[n0];
            const float zB1 = (C[nt][3] - mB) * rB * pg2[n1] + pb2[n1];
            split2(zA0, zA1, Ah[nt], Al[nt]);
            split2(zB0, zB1, Bh[nt], Bl[nt]);
        }
    }

    // =============== GEMM3: logits = z2 @ lin2w (N=16 padded) ===============
    float Y[2][4];
#pragma unroll
    for (int nt = 0; nt < 2; nt++)
#pragma unroll
        for (int j = 0; j < 4; j++) Y[nt][j] = 0.f;

#pragma unroll
    for (int ks = 0; ks < 8; ks++) {
        const uint32_t ah0 = Ah[2 * ks],     ah1 = Bh[2 * ks];
        const uint32_t ah2 = Ah[2 * ks + 1], ah3 = Bh[2 * ks + 1];
        const uint32_t al0 = Al[2 * ks],     al1 = Bl[2 * ks];
        const uint32_t al2 = Al[2 * ks + 1], al3 = Bl[2 * ks + 1];
#pragma unroll
        for (int nt = 0; nt < 2; nt++) {
            const uint4 q = *(const uint4*)(sw4 + W_B3 + (nt * 8 + g) * SWC
                                            + ks * 16 + tg * 4);
            mma_bf16(Y[nt], ah0, ah1, ah2, ah3, q.x, q.y);
            mma_bf16(Y[nt], ah0, ah1, ah2, ah3, q.z, q.w);
            mma_bf16(Y[nt], al0, al1, al2, al3, q.x, q.y);
        }
    }

    // ---- write logits ----
    {
        float* yA = g_Y + ((size_t)f * BATCH + b0 + mbase + g) * NCLASS;
        float* yB = g_Y + ((size_t)f * BATCH + b0 + mbase + g + 8) * NCLASS;
#pragma unroll
        for (int nt = 0; nt < 2; nt++) {
            const int n0 = nt * 8 + tg * 2, n1 = n0 + 1;
            if (n0 < NCLASS) {
                yA[n0] = Y[nt][0] + pl2b[n0];
                yB[n0] = Y[nt][2] + pl2b[n0];
            }
            if (n1 < NCLASS) {
                yA[n1] = Y[nt][1] + pl2b[n1];
                yB[n1] = Y[nt][3] + pl2b[n1];
            }
        }
    }
}

// ---------------------------------------------------------------------------
// Kernel 3: mean over forests, 4-way f-split per block
// ---------------------------------------------------------------------------
__global__ void mean_kernel(float* __restrict__ out)
{
    __shared__ float part[4][64];
    const int t = threadIdx.x;
    const int i = blockIdx.x * 64 + (t & 63);
    const int fg = t >> 6;
    float s = 0.f;
#pragma unroll 5
    for (int f = fg * 25; f < fg * 25 + 25; f++)
        s += g_Y[(size_t)f * (BATCH * NCLASS) + i];
    part[fg][t & 63] = s;
    __syncthreads();
    if (t < 64)
        out[blockIdx.x * 64 + t] =
            (part[0][t] + part[1][t] + part[2][t] + part[3][t]) * (1.f / NFOREST);
}

// ---------------------------------------------------------------------------
extern "C" void kernel_launch(void* const* d_in, const int* in_sizes, int n_in,
                              void* d_out, int out_size)
{
    const float* x     = (const float*)d_in[0];
    const float* w1    = (const float*)d_in[1];
    const float* b1    = (const float*)d_in[2];
    const int*   perm  = (const int*)  d_in[3];
    const float* gn1g  = (const float*)d_in[4];
    const float* gn1b  = (const float*)d_in[5];
    const float* w2a   = (const float*)d_in[6];
    const float* b2a   = (const float*)d_in[7];
    const float* gn2g  = (const float*)d_in[8];
    const float* gn2b  = (const float*)d_in[9];
    const float* w2b   = (const float*)d_in[10];
    const float* b2b   = (const float*)d_in[11];
    const float* E     = (const float*)d_in[12];
    const int*   swr   = (const int*)  d_in[13];
    const float* ln1g  = (const float*)d_in[14];
    const float* ln1b  = (const float*)d_in[15];
    const float* lin1w = (const float*)d_in[16];
    const float* lin1b = (const float*)d_in[17];
    const float* ln2g  = (const float*)d_in[18];
    const float* ln2b  = (const float*)d_in[19];
    const float* lin2w = (const float*)d_in[20];
    const float* lin2b = (const float*)d_in[21];

    const int dyn_smem = SMEM_WORDS * 4;   // 82,944 B -> 2 blocks/SM
    cudaFuncSetAttribute(forest_mma,
                         cudaFuncAttributeMaxDynamicSharedMemorySize, dyn_smem);

    cond_kernel<<<dim3(NRODT / 256, BATCH / CB), 256>>>(
        x, w1, b1, perm, gn1g, gn1b, w2a, b2a, gn2g, gn2b, w2b, b2b);
    expT_kernel<<<dim3(NRODT / 32, BATCH / 32), dim3(32, 8)>>>();
    prep_es<<<dim3(NFOREST, 16), 128>>>(E, swr);
    prep_lw<<<48, 128>>>(lin1w, lin2w);

    forest_mma<<<dim3(BATCH / 128, NFOREST), 256, dyn_smem>>>(
        swr, ln1g, ln1b, lin1b, ln2g, ln2b, lin2b);

    mean_kernel<<<BATCH * NCLASS / 64, 256>>>((float*)d_out);
}